// round 5
// baseline (speedup 1.0000x reference)
#include <cuda_runtime.h>
#include <math.h>

// NeuralODE on GB300, round 5 — single fused kernel.
// One warp = one batch element (NB=1), 128-thread blocks, 1024 blocks,
// launch_bounds(128,4) -> 4 CTAs/SM (16 warps/SM, 4/SMSP), balance 1.01.
// W1 register-resident (64 regs, K-packed u64 for fma.rn.f32x2); W2/W3/decW
// staged in smem with conflict-free 16B/lane layout, loads hoisted per kc.
// Decoder fused into the step loop (z is in smem each step) — no second
// kernel, no zs re-read.

namespace {

constexpr int kB = 4096;
constexpr int kT = 101;
constexpr int kH = 64;
constexpr int NSTEPS = kT - 1;

constexpr int WARPS = 4;
constexpr int THREADS = WARPS * 32;
constexpr int GRID = kB / WARPS;            // 1024 blocks

constexpr float A21 = 0.161f;
constexpr float A31 = -0.008480655492356989f, A32 = 0.335480655492357f;
constexpr float A41 = 2.8971530571054935f, A42 = -6.359448489975075f, A43 = 4.3622954328695815f;
constexpr float A51 = 5.325864828439257f, A52 = -11.748883564062828f;
constexpr float A53 = 7.4955393428898365f, A54 = -0.09249506636175525f;
constexpr float A61 = 5.86145544294642f, A62 = -12.92096931784711f;
constexpr float A63 = 8.159367898576159f, A64 = -0.071584973281401f, A65 = -0.028269050394068383f;
constexpr float B1c = 0.09646076681806523f, B2c = 0.01f, B3c = 0.4798896504144996f;
constexpr float B4c = 1.379008574103742f, B5c = -3.290069515436081f, B6c = 2.324710524099774f;

using u64 = unsigned long long;

__device__ __forceinline__ u64 pk(float x, float y) {
    u64 r; asm("mov.b64 %0, {%1,%2};" : "=l"(r) : "f"(x), "f"(y)); return r;
}
__device__ __forceinline__ u64 fma2(u64 a, u64 b, u64 c) {
    u64 d; asm("fma.rn.f32x2 %0, %1, %2, %3;" : "=l"(d) : "l"(a), "l"(b), "l"(c)); return d;
}
__device__ __forceinline__ float hsum2(u64 a, u64 b) {
    u64 s; asm("add.rn.f32x2 %0, %1, %2;" : "=l"(s) : "l"(a), "l"(b));
    float x, y;
    asm("mov.b64 {%0,%1}, %2;" : "=f"(x), "=f"(y) : "l"(s));
    return x + y;
}
__device__ __forceinline__ float tanh_f(float x) {
    // tanh(x) = 1 - 2/(e^{2x}+1). Correct limits at +-inf. ~1e-7 rel err.
    float ex;
    asm("ex2.approx.f32 %0, %1;" : "=f"(ex) : "f"(x * 2.885390081777927f));
    float r;
    asm("rcp.approx.f32 %0, %1;" : "=f"(r) : "f"(ex + 1.0f));
    return fmaf(-2.0f, r, 1.0f);
}

__global__ void __launch_bounds__(THREADS, 4)
node_kernel(
    const float* __restrict__ ts, const float* __restrict__ y0,
    const float* __restrict__ encW, const float* __restrict__ encb,
    const float* __restrict__ W1g, const float* __restrict__ b1g,
    const float* __restrict__ W2g, const float* __restrict__ b2g,
    const float* __restrict__ W3g, const float* __restrict__ b3g,
    const float* __restrict__ decWg, const float* __restrict__ decbg,
    float* __restrict__ ys, float* __restrict__ zs)
{
    // smem weights, [kc*32 + lane] layout: 16B per lane per kc, conflict-free.
    __shared__ __align__(16) float4 sW2q[8 * 32];    // W2[lane][4kc..4kc+4)
    __shared__ __align__(16) float4 sW3aq[8 * 32];   // W3[2lane][4kc..)
    __shared__ __align__(16) float4 sW3bq[8 * 32];   // W3[2lane+1][4kc..)
    __shared__ __align__(16) float4 sDaq[16 * 32];   // decW[2lane][4kc..)
    __shared__ __align__(16) float4 sDbq[16 * 32];   // decW[2lane+1][4kc..)
    __shared__ __align__(16) float sAct[WARPS * 128]; // per warp: u[64] h1[32] h2[32]

    const int tid = threadIdx.x;
    const int lane = tid & 31;
    const int wid = tid >> 5;
    float* su  = sAct + wid * 128;
    float* sh1 = su + 64;
    float* sh2 = su + 96;
    const int b = blockIdx.x * WARPS + wid;

    // ---- stage smem weights ----
    {
        const float4* W2f = reinterpret_cast<const float4*>(W2g);
        const float4* W3f = reinterpret_cast<const float4*>(W3g);
        const float4* Df  = reinterpret_cast<const float4*>(decWg);
        for (int i = tid; i < 256; i += THREADS) {
            int l = i >> 3, kc = i & 7;
            sW2q[kc * 32 + l]  = W2f[l * 8 + kc];
            sW3aq[kc * 32 + l] = W3f[(2 * l) * 8 + kc];
            sW3bq[kc * 32 + l] = W3f[(2 * l + 1) * 8 + kc];
        }
        for (int i = tid; i < 512; i += THREADS) {
            int l = i >> 4, kc = i & 15;
            sDaq[kc * 32 + l] = Df[(2 * l) * 16 + kc];
            sDbq[kc * 32 + l] = Df[(2 * l + 1) * 16 + kc];
        }
    }

    // ---- register-resident W1, K-packed: W1[lane][0..63] ----
    u64 w1p[32];
    {
        const ulonglong2* v1 = reinterpret_cast<const ulonglong2*>(W1g + lane * 64);
#pragma unroll
        for (int i = 0; i < 16; i++) { ulonglong2 v = v1[i]; w1p[2*i] = v.x; w1p[2*i+1] = v.y; }
    }
    const float b1r = b1g[lane];
    const float b2r = b2g[lane];
    const float2 b3p = *reinterpret_cast<const float2*>(b3g + 2 * lane);
    const float2 dbp = *reinterpret_cast<const float2*>(decbg + 2 * lane);
    const float dt = (ts[kT - 1] - ts[0]) / (float)NSTEPS;

    __syncthreads();

    // ---- encoder: z = enc(y0[b]) ----
    float z0, z1;
    {
        reinterpret_cast<float2*>(su)[lane] =
            *reinterpret_cast<const float2*>(y0 + (size_t)b * 64 + 2 * lane);
        __syncwarp();
        const ulonglong2* Ea = reinterpret_cast<const ulonglong2*>(encW + (2*lane) * 64);
        const ulonglong2* Eb = reinterpret_cast<const ulonglong2*>(encW + (2*lane+1) * 64);
        const float2 eb = *reinterpret_cast<const float2*>(encb + 2 * lane);
        u64 a0 = pk(eb.x, 0.f), a1 = 0, c0 = pk(eb.y, 0.f), c1 = 0;
        const ulonglong2* u = reinterpret_cast<const ulonglong2*>(su);
#pragma unroll
        for (int kc = 0; kc < 16; kc++) {
            ulonglong2 wA = Ea[kc], wB = Eb[kc];
            ulonglong2 v = u[kc];
            a0 = fma2(v.x, wA.x, a0); a1 = fma2(v.y, wA.y, a1);
            c0 = fma2(v.x, wB.x, c0); c1 = fma2(v.y, wB.y, c1);
        }
        z0 = hsum2(a0, a1);
        z1 = hsum2(c0, c1);
        __syncwarp();
    }

    // MLP field eval: input in su[0..63]; outputs comps (2lane, 2lane+1).
    auto mlp = [&](float& ol, float& oh) {
        const ulonglong2* uu = reinterpret_cast<const ulonglong2*>(su);
        // layer 1: 64 -> 32, tanh (W1 in regs)
        u64 a0 = pk(b1r, 0.f), a1 = 0;
#pragma unroll
        for (int kc = 0; kc < 16; kc++) {
            ulonglong2 v = uu[kc];
            a0 = fma2(v.x, w1p[2*kc], a0);
            a1 = fma2(v.y, w1p[2*kc+1], a1);
        }
        sh1[lane] = tanh_f(hsum2(a0, a1));
        __syncwarp();
        // layer 2: 32 -> 32, tanh (W2 from smem)
        const ulonglong2* h1u = reinterpret_cast<const ulonglong2*>(sh1);
        u64 c0 = pk(b2r, 0.f), c1 = 0;
#pragma unroll
        for (int kc = 0; kc < 8; kc++) {
            ulonglong2 w = reinterpret_cast<const ulonglong2*>(sW2q)[kc * 32 + lane];
            ulonglong2 v = h1u[kc];
            c0 = fma2(v.x, w.x, c0);
            c1 = fma2(v.y, w.y, c1);
        }
        sh2[lane] = tanh_f(hsum2(c0, c1));
        __syncwarp();
        // layer 3: 32 -> 64 (W3 from smem; lane owns rows 2lane, 2lane+1)
        const ulonglong2* h2u = reinterpret_cast<const ulonglong2*>(sh2);
        u64 d0 = pk(b3p.x, 0.f), d1 = 0, g0 = pk(b3p.y, 0.f), g1 = 0;
#pragma unroll
        for (int kc = 0; kc < 8; kc++) {
            ulonglong2 wa = reinterpret_cast<const ulonglong2*>(sW3aq)[kc * 32 + lane];
            ulonglong2 wb = reinterpret_cast<const ulonglong2*>(sW3bq)[kc * 32 + lane];
            ulonglong2 v = h2u[kc];
            d0 = fma2(v.x, wa.x, d0); d1 = fma2(v.y, wa.y, d1);
            g0 = fma2(v.x, wb.x, g0); g1 = fma2(v.y, wb.y, g1);
        }
        ol = hsum2(d0, d1);
        oh = hsum2(g0, g1);
    };

    auto setu = [&](float ul, float uh) {
        reinterpret_cast<float2*>(su)[lane] = make_float2(ul, uh);
        __syncwarp();
    };

    float* zrow = zs + (size_t)b * kT * kH;
    float* yrow = ys + (size_t)b * kT * kH;

    float k1l, k1h, k2l, k2h, k3l, k3h, k4l, k4h, k5l, k5h, k6l, k6h;

#pragma unroll 1
    for (int t = 0; t <= NSTEPS; t++) {
        // publish z to su; store zs; fused decode -> ys
        setu(z0, z1);
        reinterpret_cast<float2*>(zrow)[lane] = make_float2(z0, z1);
        {
            const ulonglong2* uu = reinterpret_cast<const ulonglong2*>(su);
            u64 a0 = pk(dbp.x, 0.f), a1 = 0, c0 = pk(dbp.y, 0.f), c1 = 0;
#pragma unroll
            for (int kc = 0; kc < 16; kc++) {
                ulonglong2 wa = reinterpret_cast<const ulonglong2*>(sDaq)[kc * 32 + lane];
                ulonglong2 wb = reinterpret_cast<const ulonglong2*>(sDbq)[kc * 32 + lane];
                ulonglong2 v = uu[kc];
                a0 = fma2(v.x, wa.x, a0); a1 = fma2(v.y, wa.y, a1);
                c0 = fma2(v.x, wb.x, c0); c1 = fma2(v.y, wb.y, c1);
            }
            reinterpret_cast<float2*>(yrow)[lane] =
                make_float2(hsum2(a0, a1), hsum2(c0, c1));
        }
        zrow += kH; yrow += kH;
        if (t == NSTEPS) break;

        // ---- Tsit5 stages ----
        mlp(k1l, k1h);                                     // k1 = f(z), su == z

        setu(fmaf(dt, A21 * k1l, z0), fmaf(dt, A21 * k1h, z1));
        mlp(k2l, k2h);

        {
            float al = fmaf(A32, k2l, A31 * k1l);
            float ah = fmaf(A32, k2h, A31 * k1h);
            setu(fmaf(dt, al, z0), fmaf(dt, ah, z1));
        }
        mlp(k3l, k3h);

        {
            float al = fmaf(A42, k2l, A41 * k1l); al = fmaf(A43, k3l, al);
            float ah = fmaf(A42, k2h, A41 * k1h); ah = fmaf(A43, k3h, ah);
            setu(fmaf(dt, al, z0), fmaf(dt, ah, z1));
        }
        mlp(k4l, k4h);

        {
            float al = fmaf(A52, k2l, A51 * k1l);
            al = fmaf(A53, k3l, al); al = fmaf(A54, k4l, al);
            float ah = fmaf(A52, k2h, A51 * k1h);
            ah = fmaf(A53, k3h, ah); ah = fmaf(A54, k4h, ah);
            setu(fmaf(dt, al, z0), fmaf(dt, ah, z1));
        }
        mlp(k5l, k5h);

        {
            float al = fmaf(A62, k2l, A61 * k1l); al = fmaf(A63, k3l, al);
            al = fmaf(A64, k4l, al); al = fmaf(A65, k5l, al);
            float ah = fmaf(A62, k2h, A61 * k1h); ah = fmaf(A63, k3h, ah);
            ah = fmaf(A64, k4h, ah); ah = fmaf(A65, k5h, ah);
            setu(fmaf(dt, al, z0), fmaf(dt, ah, z1));
        }
        mlp(k6l, k6h);

        {
            float s;
            s = B1c * k1l; s = fmaf(B2c, k2l, s); s = fmaf(B3c, k3l, s);
            s = fmaf(B4c, k4l, s); s = fmaf(B5c, k5l, s); s = fmaf(B6c, k6l, s);
            z0 = fmaf(dt, s, z0);
            s = B1c * k1h; s = fmaf(B2c, k2h, s); s = fmaf(B3c, k3h, s);
            s = fmaf(B4c, k4h, s); s = fmaf(B5c, k5h, s); s = fmaf(B6c, k6h, s);
            z1 = fmaf(dt, s, z1);
        }
    }
}

} // namespace

extern "C" void kernel_launch(void* const* d_in, const int* in_sizes, int n_in,
                              void* d_out, int out_size) {
    const float* ts   = (const float*)d_in[0];
    const float* y0   = (const float*)d_in[1];
    const float* encW = (const float*)d_in[2];
    const float* encb = (const float*)d_in[3];
    const float* W1   = (const float*)d_in[4];
    const float* b1   = (const float*)d_in[5];
    const float* W2   = (const float*)d_in[6];
    const float* b2   = (const float*)d_in[7];
    const float* W3   = (const float*)d_in[8];
    const float* b3   = (const float*)d_in[9];
    const float* decW = (const float*)d_in[10];
    const float* decb = (const float*)d_in[11];

    float* ys = (float*)d_out;
    float* zs = ys + (size_t)out_size / 2;     // [ys | zs]

    node_kernel<<<GRID, THREADS>>>(ts, y0, encW, encb, W1, b1, W2, b2, W3, b3,
                                   decW, decb, ys, zs);
}

// round 6
// speedup vs baseline: 1.5656x; 1.5656x over previous
#include <cuda_runtime.h>
#include <math.h>

// NeuralODE on GB300, round 6.
// ode_kernel: R3 architecture (weights register-resident K-packed u64 for
//   fma.rn.f32x2, activations broadcast via per-warp smem) with NB=3 elements
//   per warp (~230 regs, no spill) -> 3 independent latency chains per warp to
//   cover layer-boundary bubbles at the fixed 2 warps/SMSP occupancy.
//   1368 warp-tasks (tail-guarded) = 1.15 waves.
// dec_kernel: R3 smem-tile kernel + double buffering (prefetch next tile's
//   LDGs before compute; one __syncthreads per tile).

namespace {

constexpr int kB = 4096;
constexpr int kT = 101;
constexpr int kH = 64;
constexpr int NSTEPS = kT - 1;

constexpr int NB = 3;                         // elements per warp
constexpr int WARPS = 4;                      // warps per block
constexpr int THREADS = WARPS * 32;
constexpr int NTASKS = (kB + NB - 1) / NB;    // 1366 warp tasks
constexpr int GRID = (NTASKS + WARPS - 1) / WARPS;  // 342 blocks

constexpr float A21 = 0.161f;
constexpr float A31 = -0.008480655492356989f, A32 = 0.335480655492357f;
constexpr float A41 = 2.8971530571054935f, A42 = -6.359448489975075f, A43 = 4.3622954328695815f;
constexpr float A51 = 5.325864828439257f, A52 = -11.748883564062828f;
constexpr float A53 = 7.4955393428898365f, A54 = -0.09249506636175525f;
constexpr float A61 = 5.86145544294642f, A62 = -12.92096931784711f;
constexpr float A63 = 8.159367898576159f, A64 = -0.071584973281401f, A65 = -0.028269050394068383f;
constexpr float B1c = 0.09646076681806523f, B2c = 0.01f, B3c = 0.4798896504144996f;
constexpr float B4c = 1.379008574103742f, B5c = -3.290069515436081f, B6c = 2.324710524099774f;

using u64 = unsigned long long;

__device__ __forceinline__ u64 pk(float x, float y) {
    u64 r; asm("mov.b64 %0, {%1,%2};" : "=l"(r) : "f"(x), "f"(y)); return r;
}
__device__ __forceinline__ u64 fma2(u64 a, u64 b, u64 c) {
    u64 d; asm("fma.rn.f32x2 %0, %1, %2, %3;" : "=l"(d) : "l"(a), "l"(b), "l"(c)); return d;
}
__device__ __forceinline__ float hsum2(u64 a, u64 b) {
    u64 s; asm("add.rn.f32x2 %0, %1, %2;" : "=l"(s) : "l"(a), "l"(b));
    float x, y;
    asm("mov.b64 {%0,%1}, %2;" : "=f"(x), "=f"(y) : "l"(s));
    return x + y;
}
__device__ __forceinline__ float tanh_f(float x) {
    // tanh(x) = 1 - 2/(e^{2x}+1). Correct limits at +-inf. ~1e-7 rel err.
    float ex;
    asm("ex2.approx.f32 %0, %1;" : "=f"(ex) : "f"(x * 2.885390081777927f));
    float r;
    asm("rcp.approx.f32 %0, %1;" : "=f"(r) : "f"(ex + 1.0f));
    return fmaf(-2.0f, r, 1.0f);
}

__global__ void __launch_bounds__(THREADS, 2)
ode_kernel(
    const float* __restrict__ ts, const float* __restrict__ y0,
    const float* __restrict__ encW, const float* __restrict__ encb,
    const float* __restrict__ W1g, const float* __restrict__ b1g,
    const float* __restrict__ W2g, const float* __restrict__ b2g,
    const float* __restrict__ W3g, const float* __restrict__ b3g,
    float* __restrict__ zs)
{
    // per warp: su[3][64] sh1[3][32] sh2[3][32] = 384 floats
    __shared__ __align__(16) float sm[WARPS * 384];
    const int lane = threadIdx.x & 31;
    const int wid = threadIdx.x >> 5;
    float* base = sm + wid * 384;
    // su[e]=base+e*64, sh1[e]=base+192+e*32, sh2[e]=base+288+e*32
    const int b0 = (blockIdx.x * WARPS + wid) * NB;

    // ---- register-resident MLP weights, K-packed ----
    u64 w1p[32];   // W1[lane][0..63]
    u64 w2p[16];   // W2[lane][0..31]
    u64 w3a[16];   // W3[2*lane][0..31]
    u64 w3b[16];   // W3[2*lane+1][0..31]
    {
        const ulonglong2* v1 = reinterpret_cast<const ulonglong2*>(W1g + lane * 64);
#pragma unroll
        for (int i = 0; i < 16; i++) { ulonglong2 v = v1[i]; w1p[2*i] = v.x; w1p[2*i+1] = v.y; }
        const ulonglong2* v2 = reinterpret_cast<const ulonglong2*>(W2g + lane * 32);
#pragma unroll
        for (int i = 0; i < 8; i++) { ulonglong2 v = v2[i]; w2p[2*i] = v.x; w2p[2*i+1] = v.y; }
        const ulonglong2* v3a = reinterpret_cast<const ulonglong2*>(W3g + (2*lane) * 32);
        const ulonglong2* v3b = reinterpret_cast<const ulonglong2*>(W3g + (2*lane+1) * 32);
#pragma unroll
        for (int i = 0; i < 8; i++) {
            ulonglong2 a = v3a[i], b = v3b[i];
            w3a[2*i] = a.x; w3a[2*i+1] = a.y;
            w3b[2*i] = b.x; w3b[2*i+1] = b.y;
        }
    }
    const float b1r = b1g[lane];
    const float b2r = b2g[lane];
    const float2 b3p = *reinterpret_cast<const float2*>(b3g + 2 * lane);
    const float dt = (ts[kT - 1] - ts[0]) / (float)NSTEPS;

    // per-element guards (uniform across warp)
    bool live[NB];
    int bi[NB];
#pragma unroll
    for (int e = 0; e < NB; e++) {
        live[e] = (b0 + e) < kB;
        bi[e] = live[e] ? (b0 + e) : (kB - 1);
    }

    // ---- encoder for all NB elements ----
    float z0[NB], z1[NB];
    {
#pragma unroll
        for (int e = 0; e < NB; e++)
            reinterpret_cast<float2*>(base + e * 64)[lane] =
                *reinterpret_cast<const float2*>(y0 + (size_t)bi[e] * 64 + 2 * lane);
        __syncwarp();
        const ulonglong2* Ea = reinterpret_cast<const ulonglong2*>(encW + (2*lane) * 64);
        const ulonglong2* Eb = reinterpret_cast<const ulonglong2*>(encW + (2*lane+1) * 64);
        const float2 eb = *reinterpret_cast<const float2*>(encb + 2 * lane);
#pragma unroll
        for (int e = 0; e < NB; e++) {
            const ulonglong2* u = reinterpret_cast<const ulonglong2*>(base + e * 64);
            u64 a0 = pk(eb.x, 0.f), a1 = 0, c0 = pk(eb.y, 0.f), c1 = 0;
#pragma unroll
            for (int kc = 0; kc < 16; kc++) {
                ulonglong2 wA = Ea[kc], wB = Eb[kc];
                ulonglong2 v = u[kc];
                a0 = fma2(v.x, wA.x, a0); a1 = fma2(v.y, wA.y, a1);
                c0 = fma2(v.x, wB.x, c0); c1 = fma2(v.y, wB.y, c1);
            }
            z0[e] = hsum2(a0, a1);
            z1[e] = hsum2(c0, c1);
        }
        __syncwarp();
    }

    // MLP field eval for NB elements; inputs already in su[e].
    auto mlp = [&](float (&ol)[NB], float (&oh)[NB]) {
        // layer 1: 64 -> 32, tanh (W1 in regs)
        {
            u64 a0[NB], a1[NB];
#pragma unroll
            for (int e = 0; e < NB; e++) { a0[e] = pk(b1r, 0.f); a1[e] = 0; }
#pragma unroll
            for (int kc = 0; kc < 16; kc++) {
#pragma unroll
                for (int e = 0; e < NB; e++) {
                    ulonglong2 v = reinterpret_cast<const ulonglong2*>(base + e * 64)[kc];
                    a0[e] = fma2(v.x, w1p[2*kc], a0[e]);
                    a1[e] = fma2(v.y, w1p[2*kc+1], a1[e]);
                }
            }
#pragma unroll
            for (int e = 0; e < NB; e++)
                base[192 + e * 32 + lane] = tanh_f(hsum2(a0[e], a1[e]));
            __syncwarp();
        }
        // layer 2: 32 -> 32, tanh
        {
            u64 c0[NB], c1[NB];
#pragma unroll
            for (int e = 0; e < NB; e++) { c0[e] = pk(b2r, 0.f); c1[e] = 0; }
#pragma unroll
            for (int kc = 0; kc < 8; kc++) {
#pragma unroll
                for (int e = 0; e < NB; e++) {
                    ulonglong2 v = reinterpret_cast<const ulonglong2*>(base + 192 + e * 32)[kc];
                    c0[e] = fma2(v.x, w2p[2*kc], c0[e]);
                    c1[e] = fma2(v.y, w2p[2*kc+1], c1[e]);
                }
            }
#pragma unroll
            for (int e = 0; e < NB; e++)
                base[288 + e * 32 + lane] = tanh_f(hsum2(c0[e], c1[e]));
            __syncwarp();
        }
        // layer 3: 32 -> 64
        {
#pragma unroll
            for (int e = 0; e < NB; e++) {
                u64 d0 = pk(b3p.x, 0.f), d1 = 0, g0 = pk(b3p.y, 0.f), g1 = 0;
#pragma unroll
                for (int kc = 0; kc < 8; kc++) {
                    ulonglong2 v = reinterpret_cast<const ulonglong2*>(base + 288 + e * 32)[kc];
                    d0 = fma2(v.x, w3a[2*kc], d0);
                    d1 = fma2(v.y, w3a[2*kc+1], d1);
                    g0 = fma2(v.x, w3b[2*kc], g0);
                    g1 = fma2(v.y, w3b[2*kc+1], g1);
                }
                ol[e] = hsum2(d0, d1);
                oh[e] = hsum2(g0, g1);
            }
        }
    };

    float k1l[NB], k1h[NB], k2l[NB], k2h[NB], k3l[NB], k3h[NB];
    float k4l[NB], k4h[NB], k5l[NB], k5h[NB], k6l[NB], k6h[NB];

#pragma unroll 1
    for (int t = 0; t < NSTEPS; t++) {
        // store zs[b, t, :]; publish u = z
#pragma unroll
        for (int e = 0; e < NB; e++) {
            if (live[e])
                reinterpret_cast<float2*>(zs + ((size_t)bi[e] * kT + t) * kH)[lane] =
                    make_float2(z0[e], z1[e]);
            reinterpret_cast<float2*>(base + e * 64)[lane] = make_float2(z0[e], z1[e]);
        }
        __syncwarp();
        mlp(k1l, k1h);

#pragma unroll
        for (int e = 0; e < NB; e++)
            reinterpret_cast<float2*>(base + e * 64)[lane] =
                make_float2(fmaf(dt, A21 * k1l[e], z0[e]), fmaf(dt, A21 * k1h[e], z1[e]));
        __syncwarp();
        mlp(k2l, k2h);

#pragma unroll
        for (int e = 0; e < NB; e++) {
            float al = fmaf(A32, k2l[e], A31 * k1l[e]);
            float ah = fmaf(A32, k2h[e], A31 * k1h[e]);
            reinterpret_cast<float2*>(base + e * 64)[lane] =
                make_float2(fmaf(dt, al, z0[e]), fmaf(dt, ah, z1[e]));
        }
        __syncwarp();
        mlp(k3l, k3h);

#pragma unroll
        for (int e = 0; e < NB; e++) {
            float al = fmaf(A42, k2l[e], A41 * k1l[e]); al = fmaf(A43, k3l[e], al);
            float ah = fmaf(A42, k2h[e], A41 * k1h[e]); ah = fmaf(A43, k3h[e], ah);
            reinterpret_cast<float2*>(base + e * 64)[lane] =
                make_float2(fmaf(dt, al, z0[e]), fmaf(dt, ah, z1[e]));
        }
        __syncwarp();
        mlp(k4l, k4h);

#pragma unroll
        for (int e = 0; e < NB; e++) {
            float al = fmaf(A52, k2l[e], A51 * k1l[e]);
            al = fmaf(A53, k3l[e], al); al = fmaf(A54, k4l[e], al);
            float ah = fmaf(A52, k2h[e], A51 * k1h[e]);
            ah = fmaf(A53, k3h[e], ah); ah = fmaf(A54, k4h[e], ah);
            reinterpret_cast<float2*>(base + e * 64)[lane] =
                make_float2(fmaf(dt, al, z0[e]), fmaf(dt, ah, z1[e]));
        }
        __syncwarp();
        mlp(k5l, k5h);

#pragma unroll
        for (int e = 0; e < NB; e++) {
            float al = fmaf(A62, k2l[e], A61 * k1l[e]); al = fmaf(A63, k3l[e], al);
            al = fmaf(A64, k4l[e], al); al = fmaf(A65, k5l[e], al);
            float ah = fmaf(A62, k2h[e], A61 * k1h[e]); ah = fmaf(A63, k3h[e], ah);
            ah = fmaf(A64, k4h[e], ah); ah = fmaf(A65, k5h[e], ah);
            reinterpret_cast<float2*>(base + e * 64)[lane] =
                make_float2(fmaf(dt, al, z0[e]), fmaf(dt, ah, z1[e]));
        }
        __syncwarp();
        mlp(k6l, k6h);

#pragma unroll
        for (int e = 0; e < NB; e++) {
            float s;
            s = B1c * k1l[e]; s = fmaf(B2c, k2l[e], s); s = fmaf(B3c, k3l[e], s);
            s = fmaf(B4c, k4l[e], s); s = fmaf(B5c, k5l[e], s); s = fmaf(B6c, k6l[e], s);
            z0[e] = fmaf(dt, s, z0[e]);
            s = B1c * k1h[e]; s = fmaf(B2c, k2h[e], s); s = fmaf(B3c, k3h[e], s);
            s = fmaf(B4c, k4h[e], s); s = fmaf(B5c, k5h[e], s); s = fmaf(B6c, k6h[e], s);
            z1[e] = fmaf(dt, s, z1[e]);
        }
    }
#pragma unroll
    for (int e = 0; e < NB; e++)
        if (live[e])
            reinterpret_cast<float2*>(zs + ((size_t)bi[e] * kT + NSTEPS) * kH)[lane] =
                make_float2(z0[e], z1[e]);
}

// ---- decode: ys = zs @ decW^T + decb, double-buffered smem tiles ----
constexpr int DEC_THREADS = 128;
constexpr int DEC_TILE = 16;
constexpr int DEC_GRID = 592;

__global__ void __launch_bounds__(DEC_THREADS)
dec_kernel(const float* __restrict__ zs, const float* __restrict__ decW,
           const float* __restrict__ decb, float* __restrict__ ys)
{
    __shared__ __align__(16) float sz[2][DEC_TILE * 64];
    const int tid = threadIdx.x;
    const int lane = tid & 31;
    const int wid = tid >> 5;

    u64 wa[32], wb[32];
    {
        const ulonglong2* va = reinterpret_cast<const ulonglong2*>(decW + (2*lane) * 64);
        const ulonglong2* vb = reinterpret_cast<const ulonglong2*>(decW + (2*lane+1) * 64);
#pragma unroll
        for (int i = 0; i < 16; i++) {
            ulonglong2 x = va[i], y = vb[i];
            wa[2*i] = x.x; wa[2*i+1] = x.y;
            wb[2*i] = y.x; wb[2*i+1] = y.y;
        }
    }
    const float2 db = *reinterpret_cast<const float2*>(decb + 2 * lane);

    const int nTiles = (kB * kT) / DEC_TILE;
    int tile = blockIdx.x;
    float4 r0, r1;
    if (tile < nTiles) {
        const float4* g = reinterpret_cast<const float4*>(zs + (size_t)tile * DEC_TILE * 64);
        r0 = g[tid]; r1 = g[tid + 128];
    }
    int buf = 0;
#pragma unroll 1
    for (; tile < nTiles; tile += DEC_GRID, buf ^= 1) {
        float4* s4 = reinterpret_cast<float4*>(sz[buf]);
        s4[tid] = r0; s4[tid + 128] = r1;
        __syncthreads();

        // prefetch next tile while computing this one
        const int nt = tile + DEC_GRID;
        if (nt < nTiles) {
            const float4* g = reinterpret_cast<const float4*>(zs + (size_t)nt * DEC_TILE * 64);
            r0 = g[tid]; r1 = g[tid + 128];
        }

        const int r0i = wid * 4;
#pragma unroll
        for (int rr = 0; rr < 4; rr++) {
            const ulonglong2* zr = reinterpret_cast<const ulonglong2*>(sz[buf] + (r0i + rr) * 64);
            u64 a0 = pk(db.x, 0.f), a1 = 0, c0 = pk(db.y, 0.f), c1 = 0;
#pragma unroll
            for (int kc = 0; kc < 16; kc++) {
                ulonglong2 v = zr[kc];
                a0 = fma2(v.x, wa[2*kc], a0); a1 = fma2(v.y, wa[2*kc+1], a1);
                c0 = fma2(v.x, wb[2*kc], c0); c1 = fma2(v.y, wb[2*kc+1], c1);
            }
            const size_t row = (size_t)tile * DEC_TILE + r0i + rr;
            reinterpret_cast<float2*>(ys + row * 64)[lane] =
                make_float2(hsum2(a0, a1), hsum2(c0, c1));
        }
        // no trailing sync needed: next iter writes the OTHER buffer, and the
        // following wrap-around is separated by the next iteration's barrier.
    }
}

} // namespace

extern "C" void kernel_launch(void* const* d_in, const int* in_sizes, int n_in,
                              void* d_out, int out_size) {
    const float* ts   = (const float*)d_in[0];
    const float* y0   = (const float*)d_in[1];
    const float* encW = (const float*)d_in[2];
    const float* encb = (const float*)d_in[3];
    const float* W1   = (const float*)d_in[4];
    const float* b1   = (const float*)d_in[5];
    const float* W2   = (const float*)d_in[6];
    const float* b2   = (const float*)d_in[7];
    const float* W3   = (const float*)d_in[8];
    const float* b3   = (const float*)d_in[9];
    const float* decW = (const float*)d_in[10];
    const float* decb = (const float*)d_in[11];

    float* ys = (float*)d_out;
    float* zs = ys + (size_t)out_size / 2;     // [ys | zs]

    ode_kernel<<<GRID, THREADS>>>(ts, y0, encW, encb, W1, b1, W2, b2, W3, b3, zs);
    dec_kernel<<<DEC_GRID, DEC_THREADS>>>(zs, decW, decb, ys);
}

// round 7
// speedup vs baseline: 1.6994x; 1.0854x over previous
#include <cuda_runtime.h>
#include <math.h>

// NeuralODE on GB300, round 7.
// ode_kernel: R3 architecture (NB=2 per warp, weights register-resident
//   K-packed u64 for fma.rn.f32x2, activation broadcast via per-warp smem)
//   with STAGGERED element scheduling: per layer, element A's fma block, then
//   A's boundary (hsum/tanh/STS), then B's fma block (hides A's boundary
//   latency), then B's boundary, then one syncwarp.
// dec_kernel: exact R3 version (smem tile, grid 444).

namespace {

constexpr int kB = 4096;
constexpr int kT = 101;
constexpr int kH = 64;
constexpr int NSTEPS = kT - 1;

constexpr int NB = 2;
constexpr int WARPS = 4;
constexpr int THREADS = WARPS * 32;
constexpr int ELEMS_PER_BLOCK = WARPS * NB;  // 8
constexpr int GRID = kB / ELEMS_PER_BLOCK;   // 512

constexpr float A21 = 0.161f;
constexpr float A31 = -0.008480655492356989f, A32 = 0.335480655492357f;
constexpr float A41 = 2.8971530571054935f, A42 = -6.359448489975075f, A43 = 4.3622954328695815f;
constexpr float A51 = 5.325864828439257f, A52 = -11.748883564062828f;
constexpr float A53 = 7.4955393428898365f, A54 = -0.09249506636175525f;
constexpr float A61 = 5.86145544294642f, A62 = -12.92096931784711f;
constexpr float A63 = 8.159367898576159f, A64 = -0.071584973281401f, A65 = -0.028269050394068383f;
constexpr float B1c = 0.09646076681806523f, B2c = 0.01f, B3c = 0.4798896504144996f;
constexpr float B4c = 1.379008574103742f, B5c = -3.290069515436081f, B6c = 2.324710524099774f;

using u64 = unsigned long long;

__device__ __forceinline__ u64 pk(float x, float y) {
    u64 r; asm("mov.b64 %0, {%1,%2};" : "=l"(r) : "f"(x), "f"(y)); return r;
}
__device__ __forceinline__ u64 fma2(u64 a, u64 b, u64 c) {
    u64 d; asm("fma.rn.f32x2 %0, %1, %2, %3;" : "=l"(d) : "l"(a), "l"(b), "l"(c)); return d;
}
__device__ __forceinline__ float hsum2(u64 a, u64 b) {
    u64 s; asm("add.rn.f32x2 %0, %1, %2;" : "=l"(s) : "l"(a), "l"(b));
    float x, y;
    asm("mov.b64 {%0,%1}, %2;" : "=f"(x), "=f"(y) : "l"(s));
    return x + y;
}
__device__ __forceinline__ float tanh_f(float x) {
    float ex;
    asm("ex2.approx.f32 %0, %1;" : "=f"(ex) : "f"(x * 2.885390081777927f));
    float r;
    asm("rcp.approx.f32 %0, %1;" : "=f"(r) : "f"(ex + 1.0f));
    return fmaf(-2.0f, r, 1.0f);
}

__global__ void __launch_bounds__(THREADS, 2)
ode_kernel(
    const float* __restrict__ ts, const float* __restrict__ y0,
    const float* __restrict__ encW, const float* __restrict__ encb,
    const float* __restrict__ W1g, const float* __restrict__ b1g,
    const float* __restrict__ W2g, const float* __restrict__ b2g,
    const float* __restrict__ W3g, const float* __restrict__ b3g,
    float* __restrict__ zs)
{
    // per warp: suA[64] suB[64] sh1A[32] sh1B[32] sh2A[32] sh2B[32]
    __shared__ __align__(16) float sm[WARPS * 256];
    const int lane = threadIdx.x & 31;
    const int wid = threadIdx.x >> 5;
    float* suA  = sm + wid * 256;
    float* suB  = suA + 64;
    float* sh1A = suA + 128;
    float* sh1B = suA + 160;
    float* sh2A = suA + 192;
    float* sh2B = suA + 224;
    const int bA = blockIdx.x * ELEMS_PER_BLOCK + wid * NB;
    const int bB = bA + 1;

    // ---- register-resident MLP weights, K-packed ----
    u64 w1p[32], w2p[16], w3a[16], w3b[16];
    {
        const ulonglong2* v1 = reinterpret_cast<const ulonglong2*>(W1g + lane * 64);
#pragma unroll
        for (int i = 0; i < 16; i++) { ulonglong2 v = v1[i]; w1p[2*i] = v.x; w1p[2*i+1] = v.y; }
        const ulonglong2* v2 = reinterpret_cast<const ulonglong2*>(W2g + lane * 32);
#pragma unroll
        for (int i = 0; i < 8; i++) { ulonglong2 v = v2[i]; w2p[2*i] = v.x; w2p[2*i+1] = v.y; }
        const ulonglong2* v3a = reinterpret_cast<const ulonglong2*>(W3g + (2*lane) * 32);
        const ulonglong2* v3b = reinterpret_cast<const ulonglong2*>(W3g + (2*lane+1) * 32);
#pragma unroll
        for (int i = 0; i < 8; i++) {
            ulonglong2 a = v3a[i], b = v3b[i];
            w3a[2*i] = a.x; w3a[2*i+1] = a.y;
            w3b[2*i] = b.x; w3b[2*i+1] = b.y;
        }
    }
    const float b1r = b1g[lane];
    const float b2r = b2g[lane];
    const float2 b3p = *reinterpret_cast<const float2*>(b3g + 2 * lane);
    const float dt = (ts[kT - 1] - ts[0]) / (float)NSTEPS;

    // ---- encoder ----
    float zA0, zA1, zB0, zB1;
    {
        reinterpret_cast<float2*>(suA)[lane] =
            *reinterpret_cast<const float2*>(y0 + (size_t)bA * 64 + 2 * lane);
        reinterpret_cast<float2*>(suB)[lane] =
            *reinterpret_cast<const float2*>(y0 + (size_t)bB * 64 + 2 * lane);
        __syncwarp();
        const ulonglong2* Ea = reinterpret_cast<const ulonglong2*>(encW + (2*lane) * 64);
        const ulonglong2* Eb = reinterpret_cast<const ulonglong2*>(encW + (2*lane+1) * 64);
        const float2 eb = *reinterpret_cast<const float2*>(encb + 2 * lane);
        u64 aA0 = pk(eb.x, 0.f), aA1 = 0, cA0 = pk(eb.y, 0.f), cA1 = 0;
        u64 aB0 = pk(eb.x, 0.f), aB1 = 0, cB0 = pk(eb.y, 0.f), cB1 = 0;
        const ulonglong2* uA = reinterpret_cast<const ulonglong2*>(suA);
        const ulonglong2* uB = reinterpret_cast<const ulonglong2*>(suB);
#pragma unroll
        for (int kc = 0; kc < 16; kc++) {
            ulonglong2 wA = Ea[kc], wB = Eb[kc];
            ulonglong2 vA = uA[kc], vB = uB[kc];
            aA0 = fma2(vA.x, wA.x, aA0); aA1 = fma2(vA.y, wA.y, aA1);
            cA0 = fma2(vA.x, wB.x, cA0); cA1 = fma2(vA.y, wB.y, cA1);
            aB0 = fma2(vB.x, wA.x, aB0); aB1 = fma2(vB.y, wA.y, aB1);
            cB0 = fma2(vB.x, wB.x, cB0); cB1 = fma2(vB.y, wB.y, cB1);
        }
        zA0 = hsum2(aA0, aA1); zA1 = hsum2(cA0, cA1);
        zB0 = hsum2(aB0, aB1); zB1 = hsum2(cB0, cB1);
        __syncwarp();
    }

    // Staggered MLP eval: per layer, A fma -> A boundary -> B fma -> B
    // boundary -> sync. A's tanh/STS latency hides under B's fma block.
    auto mlp2 = [&](float& oAl, float& oAh, float& oBl, float& oBh) {
        // ---- layer 1 ----
        {
            const ulonglong2* uA = reinterpret_cast<const ulonglong2*>(suA);
            u64 a0 = pk(b1r, 0.f), a1 = 0;
#pragma unroll
            for (int kc = 0; kc < 16; kc++) {
                ulonglong2 v = uA[kc];
                a0 = fma2(v.x, w1p[2*kc], a0);
                a1 = fma2(v.y, w1p[2*kc+1], a1);
            }
            sh1A[lane] = tanh_f(hsum2(a0, a1));       // A boundary
            const ulonglong2* uB = reinterpret_cast<const ulonglong2*>(suB);
            u64 b0 = pk(b1r, 0.f), b1v = 0;
#pragma unroll
            for (int kc = 0; kc < 16; kc++) {
                ulonglong2 v = uB[kc];
                b0 = fma2(v.x, w1p[2*kc], b0);
                b1v = fma2(v.y, w1p[2*kc+1], b1v);
            }
            sh1B[lane] = tanh_f(hsum2(b0, b1v));      // B boundary
            __syncwarp();
        }
        // ---- layer 2 ----
        {
            const ulonglong2* hA = reinterpret_cast<const ulonglong2*>(sh1A);
            u64 a0 = pk(b2r, 0.f), a1 = 0;
#pragma unroll
            for (int kc = 0; kc < 8; kc++) {
                ulonglong2 v = hA[kc];
                a0 = fma2(v.x, w2p[2*kc], a0);
                a1 = fma2(v.y, w2p[2*kc+1], a1);
            }
            sh2A[lane] = tanh_f(hsum2(a0, a1));       // A boundary
            const ulonglong2* hB = reinterpret_cast<const ulonglong2*>(sh1B);
            u64 b0 = pk(b2r, 0.f), b1v = 0;
#pragma unroll
            for (int kc = 0; kc < 8; kc++) {
                ulonglong2 v = hB[kc];
                b0 = fma2(v.x, w2p[2*kc], b0);
                b1v = fma2(v.y, w2p[2*kc+1], b1v);
            }
            sh2B[lane] = tanh_f(hsum2(b0, b1v));      // B boundary
            __syncwarp();
        }
        // ---- layer 3 ----
        {
            const ulonglong2* hA = reinterpret_cast<const ulonglong2*>(sh2A);
            u64 d0 = pk(b3p.x, 0.f), d1 = 0, g0 = pk(b3p.y, 0.f), g1 = 0;
#pragma unroll
            for (int kc = 0; kc < 8; kc++) {
                ulonglong2 v = hA[kc];
                d0 = fma2(v.x, w3a[2*kc], d0); d1 = fma2(v.y, w3a[2*kc+1], d1);
                g0 = fma2(v.x, w3b[2*kc], g0); g1 = fma2(v.y, w3b[2*kc+1], g1);
            }
            oAl = hsum2(d0, d1); oAh = hsum2(g0, g1);
            const ulonglong2* hB = reinterpret_cast<const ulonglong2*>(sh2B);
            u64 e0 = pk(b3p.x, 0.f), e1 = 0, f0 = pk(b3p.y, 0.f), f1 = 0;
#pragma unroll
            for (int kc = 0; kc < 8; kc++) {
                ulonglong2 v = hB[kc];
                e0 = fma2(v.x, w3a[2*kc], e0); e1 = fma2(v.y, w3a[2*kc+1], e1);
                f0 = fma2(v.x, w3b[2*kc], f0); f1 = fma2(v.y, w3b[2*kc+1], f1);
            }
            oBl = hsum2(e0, e1); oBh = hsum2(f0, f1);
        }
    };

    auto setu2 = [&](float uAl, float uAh, float uBl, float uBh) {
        reinterpret_cast<float2*>(suA)[lane] = make_float2(uAl, uAh);
        reinterpret_cast<float2*>(suB)[lane] = make_float2(uBl, uBh);
        __syncwarp();
    };

    float k1Al, k1Ah, k2Al, k2Ah, k3Al, k3Ah, k4Al, k4Ah, k5Al, k5Ah, k6Al, k6Ah;
    float k1Bl, k1Bh, k2Bl, k2Bh, k3Bl, k3Bh, k4Bl, k4Bh, k5Bl, k5Bh, k6Bl, k6Bh;

#pragma unroll 1
    for (int t = 0; t < NSTEPS; t++) {
        reinterpret_cast<float2*>(zs + ((size_t)bA * kT + t) * kH)[lane] = make_float2(zA0, zA1);
        reinterpret_cast<float2*>(zs + ((size_t)bB * kT + t) * kH)[lane] = make_float2(zB0, zB1);

        setu2(zA0, zA1, zB0, zB1);
        mlp2(k1Al, k1Ah, k1Bl, k1Bh);

        setu2(fmaf(dt, A21 * k1Al, zA0), fmaf(dt, A21 * k1Ah, zA1),
              fmaf(dt, A21 * k1Bl, zB0), fmaf(dt, A21 * k1Bh, zB1));
        mlp2(k2Al, k2Ah, k2Bl, k2Bh);

        {
            float aAl = fmaf(A32, k2Al, A31 * k1Al), aAh = fmaf(A32, k2Ah, A31 * k1Ah);
            float aBl = fmaf(A32, k2Bl, A31 * k1Bl), aBh = fmaf(A32, k2Bh, A31 * k1Bh);
            setu2(fmaf(dt, aAl, zA0), fmaf(dt, aAh, zA1),
                  fmaf(dt, aBl, zB0), fmaf(dt, aBh, zB1));
        }
        mlp2(k3Al, k3Ah, k3Bl, k3Bh);

        {
            float aAl = fmaf(A42, k2Al, A41 * k1Al); aAl = fmaf(A43, k3Al, aAl);
            float aAh = fmaf(A42, k2Ah, A41 * k1Ah); aAh = fmaf(A43, k3Ah, aAh);
            float aBl = fmaf(A42, k2Bl, A41 * k1Bl); aBl = fmaf(A43, k3Bl, aBl);
            float aBh = fmaf(A42, k2Bh, A41 * k1Bh); aBh = fmaf(A43, k3Bh, aBh);
            setu2(fmaf(dt, aAl, zA0), fmaf(dt, aAh, zA1),
                  fmaf(dt, aBl, zB0), fmaf(dt, aBh, zB1));
        }
        mlp2(k4Al, k4Ah, k4Bl, k4Bh);

        {
            float aAl = fmaf(A52, k2Al, A51 * k1Al); aAl = fmaf(A53, k3Al, aAl); aAl = fmaf(A54, k4Al, aAl);
            float aAh = fmaf(A52, k2Ah, A51 * k1Ah); aAh = fmaf(A53, k3Ah, aAh); aAh = fmaf(A54, k4Ah, aAh);
            float aBl = fmaf(A52, k2Bl, A51 * k1Bl); aBl = fmaf(A53, k3Bl, aBl); aBl = fmaf(A54, k4Bl, aBl);
            float aBh = fmaf(A52, k2Bh, A51 * k1Bh); aBh = fmaf(A53, k3Bh, aBh); aBh = fmaf(A54, k4Bh, aBh);
            setu2(fmaf(dt, aAl, zA0), fmaf(dt, aAh, zA1),
                  fmaf(dt, aBl, zB0), fmaf(dt, aBh, zB1));
        }
        mlp2(k5Al, k5Ah, k5Bl, k5Bh);

        {
            float aAl = fmaf(A62, k2Al, A61 * k1Al); aAl = fmaf(A63, k3Al, aAl);
            aAl = fmaf(A64, k4Al, aAl); aAl = fmaf(A65, k5Al, aAl);
            float aAh = fmaf(A62, k2Ah, A61 * k1Ah); aAh = fmaf(A63, k3Ah, aAh);
            aAh = fmaf(A64, k4Ah, aAh); aAh = fmaf(A65, k5Ah, aAh);
            float aBl = fmaf(A62, k2Bl, A61 * k1Bl); aBl = fmaf(A63, k3Bl, aBl);
            aBl = fmaf(A64, k4Bl, aBl); aBl = fmaf(A65, k5Bl, aBl);
            float aBh = fmaf(A62, k2Bh, A61 * k1Bh); aBh = fmaf(A63, k3Bh, aBh);
            aBh = fmaf(A64, k4Bh, aBh); aBh = fmaf(A65, k5Bh, aBh);
            setu2(fmaf(dt, aAl, zA0), fmaf(dt, aAh, zA1),
                  fmaf(dt, aBl, zB0), fmaf(dt, aBh, zB1));
        }
        mlp2(k6Al, k6Ah, k6Bl, k6Bh);

        {
            float s;
            s = B1c * k1Al; s = fmaf(B2c, k2Al, s); s = fmaf(B3c, k3Al, s);
            s = fmaf(B4c, k4Al, s); s = fmaf(B5c, k5Al, s); s = fmaf(B6c, k6Al, s);
            zA0 = fmaf(dt, s, zA0);
            s = B1c * k1Ah; s = fmaf(B2c, k2Ah, s); s = fmaf(B3c, k3Ah, s);
            s = fmaf(B4c, k4Ah, s); s = fmaf(B5c, k5Ah, s); s = fmaf(B6c, k6Ah, s);
            zA1 = fmaf(dt, s, zA1);
            s = B1c * k1Bl; s = fmaf(B2c, k2Bl, s); s = fmaf(B3c, k3Bl, s);
            s = fmaf(B4c, k4Bl, s); s = fmaf(B5c, k5Bl, s); s = fmaf(B6c, k6Bl, s);
            zB0 = fmaf(dt, s, zB0);
            s = B1c * k1Bh; s = fmaf(B2c, k2Bh, s); s = fmaf(B3c, k3Bh, s);
            s = fmaf(B4c, k4Bh, s); s = fmaf(B5c, k5Bh, s); s = fmaf(B6c, k6Bh, s);
            zB1 = fmaf(dt, s, zB1);
        }
    }
    reinterpret_cast<float2*>(zs + ((size_t)bA * kT + NSTEPS) * kH)[lane] = make_float2(zA0, zA1);
    reinterpret_cast<float2*>(zs + ((size_t)bB * kT + NSTEPS) * kH)[lane] = make_float2(zB0, zB1);
}

// ---- decode: exact R3 version ----
constexpr int DEC_THREADS = 128;
constexpr int DEC_TILE = 16;
constexpr int DEC_GRID = 444;

__global__ void __launch_bounds__(DEC_THREADS)
dec_kernel(const float* __restrict__ zs, const float* __restrict__ decW,
           const float* __restrict__ decb, float* __restrict__ ys)
{
    __shared__ __align__(16) float sz[DEC_TILE * 64];
    const int tid = threadIdx.x;
    const int lane = tid & 31;
    const int wid = tid >> 5;

    u64 wa[32], wb[32];
    {
        const ulonglong2* va = reinterpret_cast<const ulonglong2*>(decW + (2*lane) * 64);
        const ulonglong2* vb = reinterpret_cast<const ulonglong2*>(decW + (2*lane+1) * 64);
#pragma unroll
        for (int i = 0; i < 16; i++) {
            ulonglong2 x = va[i], y = vb[i];
            wa[2*i] = x.x; wa[2*i+1] = x.y;
            wb[2*i] = y.x; wb[2*i+1] = y.y;
        }
    }
    const float2 db = *reinterpret_cast<const float2*>(decb + 2 * lane);

    const int nTiles = (kB * kT) / DEC_TILE;
#pragma unroll 1
    for (int tile = blockIdx.x; tile < nTiles; tile += DEC_GRID) {
        const float4* g = reinterpret_cast<const float4*>(zs + (size_t)tile * DEC_TILE * 64);
        float4* s4 = reinterpret_cast<float4*>(sz);
        s4[tid] = g[tid];
        s4[tid + 128] = g[tid + 128];
        __syncthreads();

        const int r0 = wid * 4;
#pragma unroll
        for (int rr = 0; rr < 4; rr++) {
            const ulonglong2* zr = reinterpret_cast<const ulonglong2*>(sz + (r0 + rr) * 64);
            u64 a0 = pk(db.x, 0.f), a1 = 0, c0 = pk(db.y, 0.f), c1 = 0;
#pragma unroll
            for (int kc = 0; kc < 16; kc++) {
                ulonglong2 v = zr[kc];
                a0 = fma2(v.x, wa[2*kc], a0); a1 = fma2(v.y, wa[2*kc+1], a1);
                c0 = fma2(v.x, wb[2*kc], c0); c1 = fma2(v.y, wb[2*kc+1], c1);
            }
            const size_t row = (size_t)tile * DEC_TILE + r0 + rr;
            reinterpret_cast<float2*>(ys + row * 64)[lane] =
                make_float2(hsum2(a0, a1), hsum2(c0, c1));
        }
        __syncthreads();
    }
}

} // namespace

extern "C" void kernel_launch(void* const* d_in, const int* in_sizes, int n_in,
                              void* d_out, int out_size) {
    const float* ts   = (const float*)d_in[0];
    const float* y0   = (const float*)d_in[1];
    const float* encW = (const float*)d_in[2];
    const float* encb = (const float*)d_in[3];
    const float* W1   = (const float*)d_in[4];
    const float* b1   = (const float*)d_in[5];
    const float* W2   = (const float*)d_in[6];
    const float* b2   = (const float*)d_in[7];
    const float* W3   = (const float*)d_in[8];
    const float* b3   = (const float*)d_in[9];
    const float* decW = (const float*)d_in[10];
    const float* decb = (const float*)d_in[11];

    float* ys = (float*)d_out;
    float* zs = ys + (size_t)out_size / 2;     // [ys | zs]

    ode_kernel<<<GRID, THREADS>>>(ts, y0, encW, encb, W1, b1, W2, b2, W3, b3, zs);
    dec_kernel<<<DEC_GRID, DEC_THREADS>>>(zs, decW, decb, ys);
}

// round 8
// speedup vs baseline: 1.8550x; 1.0916x over previous
#include <cuda_runtime.h>
#include <math.h>

// NeuralODE on GB300, round 8.
// ode_kernel: exact R3 version (best measured: 874us). NB=2 per warp, weights
//   register-resident K-packed u64 (fma.rn.f32x2), activation broadcast via
//   per-warp smem, interleaved A/B scheduling left to ptxas.
// dec_kernel: half-row-per-warp. Each lane owns ONE output component
//   (32 u64 weight regs), warp parity selects component half, warp pair
//   selects row half of a 16-row smem tile. ~100 regs -> 4+ CTAs/SM.

namespace {

constexpr int kB = 4096;
constexpr int kT = 101;
constexpr int kH = 64;
constexpr int NSTEPS = kT - 1;

constexpr int NB = 2;
constexpr int WARPS = 4;
constexpr int THREADS = WARPS * 32;
constexpr int ELEMS_PER_BLOCK = WARPS * NB;  // 8
constexpr int GRID = kB / ELEMS_PER_BLOCK;   // 512

constexpr float A21 = 0.161f;
constexpr float A31 = -0.008480655492356989f, A32 = 0.335480655492357f;
constexpr float A41 = 2.8971530571054935f, A42 = -6.359448489975075f, A43 = 4.3622954328695815f;
constexpr float A51 = 5.325864828439257f, A52 = -11.748883564062828f;
constexpr float A53 = 7.4955393428898365f, A54 = -0.09249506636175525f;
constexpr float A61 = 5.86145544294642f, A62 = -12.92096931784711f;
constexpr float A63 = 8.159367898576159f, A64 = -0.071584973281401f, A65 = -0.028269050394068383f;
constexpr float B1c = 0.09646076681806523f, B2c = 0.01f, B3c = 0.4798896504144996f;
constexpr float B4c = 1.379008574103742f, B5c = -3.290069515436081f, B6c = 2.324710524099774f;

using u64 = unsigned long long;

__device__ __forceinline__ u64 pk(float x, float y) {
    u64 r; asm("mov.b64 %0, {%1,%2};" : "=l"(r) : "f"(x), "f"(y)); return r;
}
__device__ __forceinline__ u64 fma2(u64 a, u64 b, u64 c) {
    u64 d; asm("fma.rn.f32x2 %0, %1, %2, %3;" : "=l"(d) : "l"(a), "l"(b), "l"(c)); return d;
}
__device__ __forceinline__ float hsum2(u64 a, u64 b) {
    u64 s; asm("add.rn.f32x2 %0, %1, %2;" : "=l"(s) : "l"(a), "l"(b));
    float x, y;
    asm("mov.b64 {%0,%1}, %2;" : "=f"(x), "=f"(y) : "l"(s));
    return x + y;
}
__device__ __forceinline__ float tanh_f(float x) {
    // tanh(x) = 1 - 2/(e^{2x}+1). Correct limits at +-inf. ~1e-7 rel err.
    float ex;
    asm("ex2.approx.f32 %0, %1;" : "=f"(ex) : "f"(x * 2.885390081777927f));
    float r;
    asm("rcp.approx.f32 %0, %1;" : "=f"(r) : "f"(ex + 1.0f));
    return fmaf(-2.0f, r, 1.0f);
}

__global__ void __launch_bounds__(THREADS, 2)
ode_kernel(
    const float* __restrict__ ts, const float* __restrict__ y0,
    const float* __restrict__ encW, const float* __restrict__ encb,
    const float* __restrict__ W1g, const float* __restrict__ b1g,
    const float* __restrict__ W2g, const float* __restrict__ b2g,
    const float* __restrict__ W3g, const float* __restrict__ b3g,
    float* __restrict__ zs)
{
    // per warp: suA[64] suB[64] sh1A[32] sh1B[32] sh2A[32] sh2B[32]
    __shared__ __align__(16) float sm[WARPS * 256];
    const int lane = threadIdx.x & 31;
    const int wid = threadIdx.x >> 5;
    float* suA  = sm + wid * 256;
    float* suB  = suA + 64;
    float* sh1A = suA + 128;
    float* sh1B = suA + 160;
    float* sh2A = suA + 192;
    float* sh2B = suA + 224;
    const int bA = blockIdx.x * ELEMS_PER_BLOCK + wid * NB;
    const int bB = bA + 1;

    // ---- register-resident MLP weights, K-packed ----
    u64 w1p[32];   // W1[lane][0..63]
    u64 w2p[16];   // W2[lane][0..31]
    u64 w3a[16];   // W3[2*lane][0..31]
    u64 w3b[16];   // W3[2*lane+1][0..31]
    {
        const ulonglong2* v1 = reinterpret_cast<const ulonglong2*>(W1g + lane * 64);
#pragma unroll
        for (int i = 0; i < 16; i++) { ulonglong2 v = v1[i]; w1p[2*i] = v.x; w1p[2*i+1] = v.y; }
        const ulonglong2* v2 = reinterpret_cast<const ulonglong2*>(W2g + lane * 32);
#pragma unroll
        for (int i = 0; i < 8; i++) { ulonglong2 v = v2[i]; w2p[2*i] = v.x; w2p[2*i+1] = v.y; }
        const ulonglong2* v3a = reinterpret_cast<const ulonglong2*>(W3g + (2*lane) * 32);
        const ulonglong2* v3b = reinterpret_cast<const ulonglong2*>(W3g + (2*lane+1) * 32);
#pragma unroll
        for (int i = 0; i < 8; i++) {
            ulonglong2 a = v3a[i], b = v3b[i];
            w3a[2*i] = a.x; w3a[2*i+1] = a.y;
            w3b[2*i] = b.x; w3b[2*i+1] = b.y;
        }
    }
    const float b1r = b1g[lane];
    const float b2r = b2g[lane];
    const float2 b3p = *reinterpret_cast<const float2*>(b3g + 2 * lane);
    const float dt = (ts[kT - 1] - ts[0]) / (float)NSTEPS;

    // ---- encoder for both elements ----
    float zA0, zA1, zB0, zB1;
    {
        reinterpret_cast<float2*>(suA)[lane] =
            *reinterpret_cast<const float2*>(y0 + (size_t)bA * 64 + 2 * lane);
        reinterpret_cast<float2*>(suB)[lane] =
            *reinterpret_cast<const float2*>(y0 + (size_t)bB * 64 + 2 * lane);
        __syncwarp();
        const ulonglong2* Ea = reinterpret_cast<const ulonglong2*>(encW + (2*lane) * 64);
        const ulonglong2* Eb = reinterpret_cast<const ulonglong2*>(encW + (2*lane+1) * 64);
        const float2 eb = *reinterpret_cast<const float2*>(encb + 2 * lane);
        u64 aA0 = pk(eb.x, 0.f), aA1 = 0, cA0 = pk(eb.y, 0.f), cA1 = 0;
        u64 aB0 = pk(eb.x, 0.f), aB1 = 0, cB0 = pk(eb.y, 0.f), cB1 = 0;
        const ulonglong2* uA = reinterpret_cast<const ulonglong2*>(suA);
        const ulonglong2* uB = reinterpret_cast<const ulonglong2*>(suB);
#pragma unroll
        for (int kc = 0; kc < 16; kc++) {
            ulonglong2 wA = Ea[kc], wB = Eb[kc];
            ulonglong2 vA = uA[kc], vB = uB[kc];
            aA0 = fma2(vA.x, wA.x, aA0); aA1 = fma2(vA.y, wA.y, aA1);
            cA0 = fma2(vA.x, wB.x, cA0); cA1 = fma2(vA.y, wB.y, cA1);
            aB0 = fma2(vB.x, wA.x, aB0); aB1 = fma2(vB.y, wA.y, aB1);
            cB0 = fma2(vB.x, wB.x, cB0); cB1 = fma2(vB.y, wB.y, cB1);
        }
        zA0 = hsum2(aA0, aA1); zA1 = hsum2(cA0, cA1);
        zB0 = hsum2(aB0, aB1); zB1 = hsum2(cB0, cB1);
        __syncwarp();
    }

    // MLP field eval for both elements; input in suA/suB.
    auto mlp2 = [&](float& oAl, float& oAh, float& oBl, float& oBh) {
        // layer 1: 64 -> 32, tanh
        u64 aA0 = pk(b1r, 0.f), aA1 = 0, aB0 = pk(b1r, 0.f), aB1 = 0;
        {
            const ulonglong2* uA = reinterpret_cast<const ulonglong2*>(suA);
            const ulonglong2* uB = reinterpret_cast<const ulonglong2*>(suB);
#pragma unroll
            for (int kc = 0; kc < 16; kc++) {
                ulonglong2 vA = uA[kc], vB = uB[kc];
                aA0 = fma2(vA.x, w1p[2*kc], aA0); aA1 = fma2(vA.y, w1p[2*kc+1], aA1);
                aB0 = fma2(vB.x, w1p[2*kc], aB0); aB1 = fma2(vB.y, w1p[2*kc+1], aB1);
            }
        }
        sh1A[lane] = tanh_f(hsum2(aA0, aA1));
        sh1B[lane] = tanh_f(hsum2(aB0, aB1));
        __syncwarp();
        // layer 2: 32 -> 32, tanh
        u64 cA0 = pk(b2r, 0.f), cA1 = 0, cB0 = pk(b2r, 0.f), cB1 = 0;
        {
            const ulonglong2* hA = reinterpret_cast<const ulonglong2*>(sh1A);
            const ulonglong2* hB = reinterpret_cast<const ulonglong2*>(sh1B);
#pragma unroll
            for (int kc = 0; kc < 8; kc++) {
                ulonglong2 vA = hA[kc], vB = hB[kc];
                cA0 = fma2(vA.x, w2p[2*kc], cA0); cA1 = fma2(vA.y, w2p[2*kc+1], cA1);
                cB0 = fma2(vB.x, w2p[2*kc], cB0); cB1 = fma2(vB.y, w2p[2*kc+1], cB1);
            }
        }
        sh2A[lane] = tanh_f(hsum2(cA0, cA1));
        sh2B[lane] = tanh_f(hsum2(cB0, cB1));
        __syncwarp();
        // layer 3: 32 -> 64 (lane outputs comps 2*lane, 2*lane+1)
        u64 dA0 = pk(b3p.x, 0.f), dA1 = 0, eA0 = pk(b3p.y, 0.f), eA1 = 0;
        u64 dB0 = pk(b3p.x, 0.f), dB1 = 0, eB0 = pk(b3p.y, 0.f), eB1 = 0;
        {
            const ulonglong2* hA = reinterpret_cast<const ulonglong2*>(sh2A);
            const ulonglong2* hB = reinterpret_cast<const ulonglong2*>(sh2B);
#pragma unroll
            for (int kc = 0; kc < 8; kc++) {
                ulonglong2 vA = hA[kc], vB = hB[kc];
                dA0 = fma2(vA.x, w3a[2*kc], dA0); dA1 = fma2(vA.y, w3a[2*kc+1], dA1);
                eA0 = fma2(vA.x, w3b[2*kc], eA0); eA1 = fma2(vA.y, w3b[2*kc+1], eA1);
                dB0 = fma2(vB.x, w3a[2*kc], dB0); dB1 = fma2(vB.y, w3a[2*kc+1], dB1);
                eB0 = fma2(vB.x, w3b[2*kc], eB0); eB1 = fma2(vB.y, w3b[2*kc+1], eB1);
            }
        }
        oAl = hsum2(dA0, dA1); oAh = hsum2(eA0, eA1);
        oBl = hsum2(dB0, dB1); oBh = hsum2(eB0, eB1);
    };

    auto setu2 = [&](float uAl, float uAh, float uBl, float uBh) {
        reinterpret_cast<float2*>(suA)[lane] = make_float2(uAl, uAh);
        reinterpret_cast<float2*>(suB)[lane] = make_float2(uBl, uBh);
        __syncwarp();
    };

    float k1Al, k1Ah, k2Al, k2Ah, k3Al, k3Ah, k4Al, k4Ah, k5Al, k5Ah, k6Al, k6Ah;
    float k1Bl, k1Bh, k2Bl, k2Bh, k3Bl, k3Bh, k4Bl, k4Bh, k5Bl, k5Bh, k6Bl, k6Bh;

#pragma unroll 1
    for (int t = 0; t < NSTEPS; t++) {
        reinterpret_cast<float2*>(zs + ((size_t)bA * kT + t) * kH)[lane] = make_float2(zA0, zA1);
        reinterpret_cast<float2*>(zs + ((size_t)bB * kT + t) * kH)[lane] = make_float2(zB0, zB1);

        setu2(zA0, zA1, zB0, zB1);
        mlp2(k1Al, k1Ah, k1Bl, k1Bh);

        setu2(fmaf(dt, A21 * k1Al, zA0), fmaf(dt, A21 * k1Ah, zA1),
              fmaf(dt, A21 * k1Bl, zB0), fmaf(dt, A21 * k1Bh, zB1));
        mlp2(k2Al, k2Ah, k2Bl, k2Bh);

        {
            float aAl = fmaf(A32, k2Al, A31 * k1Al), aAh = fmaf(A32, k2Ah, A31 * k1Ah);
            float aBl = fmaf(A32, k2Bl, A31 * k1Bl), aBh = fmaf(A32, k2Bh, A31 * k1Bh);
            setu2(fmaf(dt, aAl, zA0), fmaf(dt, aAh, zA1),
                  fmaf(dt, aBl, zB0), fmaf(dt, aBh, zB1));
        }
        mlp2(k3Al, k3Ah, k3Bl, k3Bh);

        {
            float aAl = fmaf(A42, k2Al, A41 * k1Al); aAl = fmaf(A43, k3Al, aAl);
            float aAh = fmaf(A42, k2Ah, A41 * k1Ah); aAh = fmaf(A43, k3Ah, aAh);
            float aBl = fmaf(A42, k2Bl, A41 * k1Bl); aBl = fmaf(A43, k3Bl, aBl);
            float aBh = fmaf(A42, k2Bh, A41 * k1Bh); aBh = fmaf(A43, k3Bh, aBh);
            setu2(fmaf(dt, aAl, zA0), fmaf(dt, aAh, zA1),
                  fmaf(dt, aBl, zB0), fmaf(dt, aBh, zB1));
        }
        mlp2(k4Al, k4Ah, k4Bl, k4Bh);

        {
            float aAl = fmaf(A52, k2Al, A51 * k1Al); aAl = fmaf(A53, k3Al, aAl); aAl = fmaf(A54, k4Al, aAl);
            float aAh = fmaf(A52, k2Ah, A51 * k1Ah); aAh = fmaf(A53, k3Ah, aAh); aAh = fmaf(A54, k4Ah, aAh);
            float aBl = fmaf(A52, k2Bl, A51 * k1Bl); aBl = fmaf(A53, k3Bl, aBl); aBl = fmaf(A54, k4Bl, aBl);
            float aBh = fmaf(A52, k2Bh, A51 * k1Bh); aBh = fmaf(A53, k3Bh, aBh); aBh = fmaf(A54, k4Bh, aBh);
            setu2(fmaf(dt, aAl, zA0), fmaf(dt, aAh, zA1),
                  fmaf(dt, aBl, zB0), fmaf(dt, aBh, zB1));
        }
        mlp2(k5Al, k5Ah, k5Bl, k5Bh);

        {
            float aAl = fmaf(A62, k2Al, A61 * k1Al); aAl = fmaf(A63, k3Al, aAl);
            aAl = fmaf(A64, k4Al, aAl); aAl = fmaf(A65, k5Al, aAl);
            float aAh = fmaf(A62, k2Ah, A61 * k1Ah); aAh = fmaf(A63, k3Ah, aAh);
            aAh = fmaf(A64, k4Ah, aAh); aAh = fmaf(A65, k5Ah, aAh);
            float aBl = fmaf(A62, k2Bl, A61 * k1Bl); aBl = fmaf(A63, k3Bl, aBl);
            aBl = fmaf(A64, k4Bl, aBl); aBl = fmaf(A65, k5Bl, aBl);
            float aBh = fmaf(A62, k2Bh, A61 * k1Bh); aBh = fmaf(A63, k3Bh, aBh);
            aBh = fmaf(A64, k4Bh, aBh); aBh = fmaf(A65, k5Bh, aBh);
            setu2(fmaf(dt, aAl, zA0), fmaf(dt, aAh, zA1),
                  fmaf(dt, aBl, zB0), fmaf(dt, aBh, zB1));
        }
        mlp2(k6Al, k6Ah, k6Bl, k6Bh);

        {
            float s;
            s = B1c * k1Al; s = fmaf(B2c, k2Al, s); s = fmaf(B3c, k3Al, s);
            s = fmaf(B4c, k4Al, s); s = fmaf(B5c, k5Al, s); s = fmaf(B6c, k6Al, s);
            zA0 = fmaf(dt, s, zA0);
            s = B1c * k1Ah; s = fmaf(B2c, k2Ah, s); s = fmaf(B3c, k3Ah, s);
            s = fmaf(B4c, k4Ah, s); s = fmaf(B5c, k5Ah, s); s = fmaf(B6c, k6Ah, s);
            zA1 = fmaf(dt, s, zA1);
            s = B1c * k1Bl; s = fmaf(B2c, k2Bl, s); s = fmaf(B3c, k3Bl, s);
            s = fmaf(B4c, k4Bl, s); s = fmaf(B5c, k5Bl, s); s = fmaf(B6c, k6Bl, s);
            zB0 = fmaf(dt, s, zB0);
            s = B1c * k1Bh; s = fmaf(B2c, k2Bh, s); s = fmaf(B3c, k3Bh, s);
            s = fmaf(B4c, k4Bh, s); s = fmaf(B5c, k5Bh, s); s = fmaf(B6c, k6Bh, s);
            zB1 = fmaf(dt, s, zB1);
        }
    }
    reinterpret_cast<float2*>(zs + ((size_t)bA * kT + NSTEPS) * kH)[lane] = make_float2(zA0, zA1);
    reinterpret_cast<float2*>(zs + ((size_t)bB * kT + NSTEPS) * kH)[lane] = make_float2(zB0, zB1);
}

// ---- decode: half-row-per-warp, low-register, high-occupancy ----
// Warp parity -> component half [0:32) or [32:64); warp pair -> row half
// [0:8) or [8:16) of the 16-row tile. Each lane owns ONE output component:
// 32 u64 weight regs -> ~100 regs total -> 4+ CTAs/SM.
constexpr int DEC_THREADS = 128;
constexpr int DEC_TILE = 16;
constexpr int DEC_GRID = 444;

__global__ void __launch_bounds__(DEC_THREADS, 4)
dec_kernel(const float* __restrict__ zs, const float* __restrict__ decW,
           const float* __restrict__ decb, float* __restrict__ ys)
{
    __shared__ __align__(16) float sz[DEC_TILE * 64];
    const int tid = threadIdx.x;
    const int lane = tid & 31;
    const int wid = tid >> 5;
    const int half = (wid & 1) * 32;        // component offset
    const int rbase = (wid >> 1) * 8;       // row offset in tile

    // lane owns output component (half + lane): one decW row, K-packed
    u64 w[32];
    {
        const ulonglong2* vw = reinterpret_cast<const ulonglong2*>(decW + (half + lane) * 64);
#pragma unroll
        for (int i = 0; i < 16; i++) { ulonglong2 v = vw[i]; w[2*i] = v.x; w[2*i+1] = v.y; }
    }
    const float db = decb[half + lane];

    const int nTiles = (kB * kT) / DEC_TILE;   // 25856
#pragma unroll 1
    for (int tile = blockIdx.x; tile < nTiles; tile += DEC_GRID) {
        // stage 16 rows (4KB) coalesced
        const float4* g = reinterpret_cast<const float4*>(zs + (size_t)tile * DEC_TILE * 64);
        float4* s4 = reinterpret_cast<float4*>(sz);
        s4[tid] = g[tid];
        s4[tid + 128] = g[tid + 128];
        __syncthreads();

#pragma unroll 2
        for (int rr = 0; rr < 8; rr++) {
            const ulonglong2* zr = reinterpret_cast<const ulonglong2*>(sz + (rbase + rr) * 64);
            u64 a0 = pk(db, 0.f), a1 = 0;
#pragma unroll
            for (int kc = 0; kc < 16; kc++) {
                ulonglong2 v = zr[kc];
                a0 = fma2(v.x, w[2*kc], a0);
                a1 = fma2(v.y, w[2*kc+1], a1);
            }
            const size_t row = (size_t)tile * DEC_TILE + rbase + rr;
            ys[row * 64 + half + lane] = hsum2(a0, a1);
        }
        __syncthreads();
    }
}

} // namespace

extern "C" void kernel_launch(void* const* d_in, const int* in_sizes, int n_in,
                              void* d_out, int out_size) {
    const float* ts   = (const float*)d_in[0];
    const float* y0   = (const float*)d_in[1];
    const float* encW = (const float*)d_in[2];
    const float* encb = (const float*)d_in[3];
    const float* W1   = (const float*)d_in[4];
    const float* b1   = (const float*)d_in[5];
    const float* W2   = (const float*)d_in[6];
    const float* b2   = (const float*)d_in[7];
    const float* W3   = (const float*)d_in[8];
    const float* b3   = (const float*)d_in[9];
    const float* decW = (const float*)d_in[10];
    const float* decb = (const float*)d_in[11];

    float* ys = (float*)d_out;
    float* zs = ys + (size_t)out_size / 2;     // [ys | zs]

    ode_kernel<<<GRID, THREADS>>>(ts, y0, encW, encb, W1, b1, W2, b2, W3, b3, zs);
    dec_kernel<<<DEC_GRID, DEC_THREADS>>>(zs, decW, decb, ys);
}